// round 5
// baseline (speedup 1.0000x reference)
#include <cuda_runtime.h>
#include <math.h>

#define BS 64
#define SEQ 300
#define D 768
#define G 2304          // 3*D
#define TSTEPS 100
#define MTOT (BS*SEQ)   // 19200
#define NB 288
#define NT 256

// ---------------- device scratch (no allocations allowed) ----------------
__device__ __align__(16) float g_xpe[(size_t)MTOT * D];
__device__ __align__(16) float g_gi [(size_t)MTOT * G];
__device__ __align__(16) float g_enc[(size_t)MTOT * D];
__device__ __align__(16) float g_mem[(size_t)MTOT * D];
__device__ __align__(16) float g_h[BS * D];
__device__ __align__(16) float g_part [4 * BS * G];     // split-K partials (enc gh / dec gi)
__device__ __align__(16) float g_part2[2 * BS * G];     // dec gh partials
__device__ __align__(16) float g_qpart[12 * BS * D];
__device__ __align__(16) float g_logits[BS * SEQ];
__device__ __align__(16) float g_ctxp[2][BS * D];       // ctx halves (softmax-normalized)
__device__ __align__(16) float g_decWc[(size_t)G * D];  // dec_Wih[:,1:] repacked
__device__ unsigned g_bar_count;
__device__ unsigned g_bar_gen;

// ---------------- grid barrier (all blocks co-resident) ----------------
__device__ __forceinline__ void grid_barrier() {
    __syncthreads();
    if (threadIdx.x == 0) {
        __threadfence();
        unsigned gen = *(volatile unsigned*)&g_bar_gen;
        unsigned nb = gridDim.x;
        if (atomicAdd(&g_bar_count, 1u) == nb - 1u) {
            *(volatile unsigned*)&g_bar_count = 0u;
            __threadfence();
            *(volatile unsigned*)&g_bar_gen = gen + 1u;
        } else {
            while (*(volatile unsigned*)&g_bar_gen == gen) { __nanosleep(32); }
        }
    }
    __syncthreads();
}

// ---------------- fast transcendentals (evidence: output insensitive at 1e-7 level) ----
__device__ __forceinline__ float sigx(float x)  { return __fdividef(1.0f, 1.0f + __expf(-x)); }
__device__ __forceinline__ float tanhx(float x) { return 1.0f - __fdividef(2.0f, __expf(2.0f * x) + 1.0f); }

__device__ __forceinline__ float4 ldcg4(const float* p) {
    return __ldcg(reinterpret_cast<const float4*>(p));
}

// ---------------- block reductions (256 threads) ----------------
__device__ __forceinline__ float blockReduceSum256(float v, float* red) {
    __syncthreads();
    int lane = threadIdx.x & 31, w = threadIdx.x >> 5;
#pragma unroll
    for (int o = 16; o; o >>= 1) v += __shfl_down_sync(0xffffffffu, v, o);
    if (lane == 0) red[w] = v;
    __syncthreads();
    if (w == 0) {
        float r = (lane < 8) ? red[lane] : 0.0f;
#pragma unroll
        for (int o = 4; o; o >>= 1) r += __shfl_down_sync(0xffffffffu, r, o);
        if (lane == 0) red[0] = r;
    }
    __syncthreads();
    return red[0];
}

__device__ __forceinline__ float blockReduceMax256(float v, float* red) {
    __syncthreads();
    int lane = threadIdx.x & 31, w = threadIdx.x >> 5;
#pragma unroll
    for (int o = 16; o; o >>= 1) v = fmaxf(v, __shfl_down_sync(0xffffffffu, v, o));
    if (lane == 0) red[w] = v;
    __syncthreads();
    if (w == 0) {
        float r = (lane < 8) ? red[lane] : -1e30f;
#pragma unroll
        for (int o = 4; o; o >>= 1) r = fmaxf(r, __shfl_down_sync(0xffffffffu, r, o));
        if (lane == 0) red[0] = r;
    }
    __syncthreads();
    return red[0];
}

// ---------------- persistent small-M GEMM tile: Cp[64, n0..n0+31] = A[64,kslice] * B^T ----
__device__ void pgemm(const float* __restrict__ A, const float* __restrict__ A2,
                      const float* __restrict__ B, float* __restrict__ Cp,
                      int lda, int ldb, int ldc, int n0, int kbeg, int kc,
                      float (*As)[65], float (*Bs)[36])
{
    const int tid = threadIdx.x;
    const int alr = tid & 63;
    const int alk = (tid >> 6) << 2;
    const int brb = tid & 31;
    const int bkb = ((tid >> 5) & 3) << 2;
    const int tr  = tid >> 3;   // 0..31
    const int tc  = tid & 7;    // 0..7
    float a00=0,a01=0,a02=0,a03=0,a10=0,a11=0,a12=0,a13=0;
    const float* Ap  = A + (size_t)alr * lda + kbeg + alk;
    const float* A2p = A2 ? A2 + (size_t)alr * lda + kbeg + alk : nullptr;
    const float* Bp  = B + (size_t)(n0 + brb) * ldb + kbeg + bkb;

    for (int k0 = 0; k0 < kc; k0 += 16) {
        float4 a4 = ldcg4(Ap + k0);
        if (A2p) { float4 y = ldcg4(A2p + k0); a4.x += y.x; a4.y += y.y; a4.z += y.z; a4.w += y.w; }
        As[alk + 0][alr] = a4.x; As[alk + 1][alr] = a4.y;
        As[alk + 2][alr] = a4.z; As[alk + 3][alr] = a4.w;
        if (tid < 128) {
            float4 b4 = *reinterpret_cast<const float4*>(Bp + k0);
            Bs[bkb + 0][brb] = b4.x; Bs[bkb + 1][brb] = b4.y;
            Bs[bkb + 2][brb] = b4.z; Bs[bkb + 3][brb] = b4.w;
        }
        __syncthreads();
#pragma unroll
        for (int kk = 0; kk < 16; kk++) {
            float r0 = As[kk][2 * tr], r1 = As[kk][2 * tr + 1];
            float4 bv = *reinterpret_cast<const float4*>(&Bs[kk][tc << 2]);
            a00 += r0 * bv.x; a01 += r0 * bv.y; a02 += r0 * bv.z; a03 += r0 * bv.w;
            a10 += r1 * bv.x; a11 += r1 * bv.y; a12 += r1 * bv.z; a13 += r1 * bv.w;
        }
        __syncthreads();
    }
    float4 v0 = make_float4(a00, a01, a02, a03);
    float4 v1 = make_float4(a10, a11, a12, a13);
    *reinterpret_cast<float4*>(&Cp[(size_t)(2 * tr)     * ldc + n0 + (tc << 2)]) = v0;
    *reinterpret_cast<float4*>(&Cp[(size_t)(2 * tr + 1) * ldc + n0 + (tc << 2)]) = v1;
}

// ---------------- prep: PE add + dec_Wih repack + zero h ----------------
__global__ void prep_kernel(const float* __restrict__ x, const float* __restrict__ dWih) {
    size_t idx = (size_t)blockIdx.x * blockDim.x + threadIdx.x;
    if (idx < (size_t)MTOT * D) {
        int k = (int)(idx % D);
        int s = (int)((idx / D) % SEQ);
        const float c = 9.210340371976184f / (float)D;  // ln(10000)/d
        int keven = k & ~1;
        float dv  = expf(-(float)keven * c);
        float arg = (float)s * dv;
        float pe  = (k & 1) ? cosf(arg) : sinf(arg);
        g_xpe[idx] = x[idx] + pe;
    }
    if (idx < (size_t)G * D) {
        int g = (int)(idx / D), k = (int)(idx % D);
        g_decWc[idx] = dWih[(size_t)g * (D + 1) + 1 + k];
    }
    if (idx < BS * D) g_h[idx] = 0.0f;
}

// ---------------- big SGEMM: C[M,N] = A[M,K] * B[N,K]^T + bias[n] ----------------
__device__ __forceinline__ void sgemm_body(const float* __restrict__ A,
                                           const float* __restrict__ B,
                                           const float* __restrict__ bias,
                                           float* __restrict__ C,
                                           int N, int K) {
    __shared__ __align__(16) float As[16][68];
    __shared__ __align__(16) float Bs[16][68];
    const int tid = threadIdx.x;
    const int m0 = blockIdx.y * 64;
    const int n0 = blockIdx.x * 64;
    const int tr = tid >> 4;
    const int tc = tid & 15;
    const int lr = tid >> 2;
    const int lk = (tid & 3) << 2;
    float acc[4][4];
#pragma unroll
    for (int i = 0; i < 4; i++)
#pragma unroll
        for (int j = 0; j < 4; j++) acc[i][j] = 0.0f;

    const float* Arow = A + (size_t)(m0 + lr) * K + lk;
    const float* Brow = B + (size_t)(n0 + lr) * K + lk;

    for (int k0 = 0; k0 < K; k0 += 16) {
        float4 a4 = *(const float4*)(Arow + k0);
        float4 b4 = *(const float4*)(Brow + k0);
        As[lk + 0][lr] = a4.x; As[lk + 1][lr] = a4.y; As[lk + 2][lr] = a4.z; As[lk + 3][lr] = a4.w;
        Bs[lk + 0][lr] = b4.x; Bs[lk + 1][lr] = b4.y; Bs[lk + 2][lr] = b4.z; Bs[lk + 3][lr] = b4.w;
        __syncthreads();
#pragma unroll
        for (int kk = 0; kk < 16; kk++) {
            float4 av = *(const float4*)&As[kk][tr << 2];
            float4 bv = *(const float4*)&Bs[kk][tc << 2];
            float a[4] = {av.x, av.y, av.z, av.w};
            float bb[4] = {bv.x, bv.y, bv.z, bv.w};
#pragma unroll
            for (int i = 0; i < 4; i++)
#pragma unroll
                for (int j = 0; j < 4; j++) acc[i][j] += a[i] * bb[j];
        }
        __syncthreads();
    }
    int n = n0 + (tc << 2);
#pragma unroll
    for (int i = 0; i < 4; i++) {
        float4 v;
        v.x = acc[i][0] + bias[n + 0];
        v.y = acc[i][1] + bias[n + 1];
        v.z = acc[i][2] + bias[n + 2];
        v.w = acc[i][3] + bias[n + 3];
        *(float4*)&C[(size_t)(m0 + (tr << 2) + i) * N + n] = v;
    }
}

__global__ __launch_bounds__(256) void sgemm_gi_kernel(const float* __restrict__ W,
                                                       const float* __restrict__ bias) {
    sgemm_body(g_xpe, W, bias, g_gi, G, D);
}
__global__ __launch_bounds__(256) void sgemm_mem_kernel(const float* __restrict__ W,
                                                        const float* __restrict__ bias) {
    sgemm_body(g_enc, W, bias, g_mem, D, D);
}

// ---------------- persistent encoder: 300 GRU steps ----------------
__global__ __launch_bounds__(NT, 2) void encoder_kernel(const float* __restrict__ Whh,
                                                        const float* __restrict__ bhh)
{
    __shared__ __align__(16) float As[16][65];
    __shared__ __align__(16) float Bs[16][36];
    const int bx = blockIdx.x;
    const int tid = threadIdx.x;
    const int nt = bx % 72, kz = bx / 72;       // 72 n-tiles x 4 split-K
    const int n0 = nt * 32, kbeg = kz * 192;
    float* Cp = g_part + (size_t)(kz * BS) * G;
    const int idx = bx * NT + tid;

    for (int s = 0; s < SEQ; s++) {
        pgemm(g_h, nullptr, Whh, Cp, D, D, G, n0, kbeg, 192, As, Bs);
        grid_barrier();
        if (idx < BS * D) {
            int b = idx / D, j = idx - b * D;
            size_t gib = ((size_t)b * SEQ + s) * G;
            float gr = g_gi[gib + j];
            float gz = g_gi[gib + D + j];
            float gn = g_gi[gib + 2 * D + j];
            float t0 = 0.f, t1 = 0.f, t2 = 0.f;
#pragma unroll
            for (int z = 0; z < 4; z++) {
                const float* P = g_part + (size_t)(z * BS + b) * G;
                t0 += __ldcg(P + j); t1 += __ldcg(P + D + j); t2 += __ldcg(P + 2 * D + j);
            }
            float r  = sigx(gr + bhh[j] + t0);
            float zt = sigx(gz + bhh[D + j] + t1);
            float n  = tanhx(gn + r * (bhh[2 * D + j] + t2));
            float hp = __ldcg(&g_h[idx]);
            float hn = (1.0f - zt) * n + zt * hp;
            g_h[idx] = hn;
            g_enc[((size_t)b * SEQ + s) * D + j] = hn;
        }
        grid_barrier();
    }
}

// ---------------- persistent decoder: 100 steps ----------------
__global__ __launch_bounds__(NT, 2) void decoder_kernel(
    const float* __restrict__ qW,  const float* __restrict__ qb,
    const float* __restrict__ pW,  const float* __restrict__ pb,
    const float* __restrict__ dWih, const float* __restrict__ dWhh,
    const float* __restrict__ bih, const float* __restrict__ bhh,
    const float* __restrict__ tW,  const float* __restrict__ tb,
    float* __restrict__ out)
{
    __shared__ __align__(16) float As[16][65];
    __shared__ __align__(16) float Bs[16][36];
    __shared__ float s_q[D];
    __shared__ float s_pw[D];
    __shared__ float s_w[SEQ];
    __shared__ float red[8];
    const int bx = blockIdx.x, tid = threadIdx.x;

    // CRITICAL FIX: reference decoder starts from h0 = zeros, not the encoder's
    // final hidden state. Zero g_h before the first decoder step.
    {
        const int idx = bx * NT + tid;
        if (idx < BS * D) g_h[idx] = 0.0f;
    }
    grid_barrier();

    for (int t = 0; t < TSTEPS; t++) {
        // P1: qpart = h @ qW^T   (24 n-tiles x 12 split-K)
        {
            int nt = bx % 24, kz = bx / 24;
            pgemm(g_h, nullptr, qW, g_qpart + (size_t)(kz * BS) * D,
                  D, D, D, nt * 32, kz * 64, 64, As, Bs);
        }
        grid_barrier();
        // P2: logits (128 blocks)  ||  gh = h @ dWhh^T (144 blocks)
        if (bx < 128) {
            int b = bx >> 1, half = bx & 1;
            for (int j = tid; j < D; j += NT) {
                float v = qb[j];
#pragma unroll
                for (int z = 0; z < 12; z++) v += __ldcg(&g_qpart[(size_t)(z * BS + b) * D + j]);
                s_q[j]  = v;
                s_pw[j] = pW[j];
            }
            __syncthreads();
            int w = tid >> 5, lane = tid & 31;
            float pb0 = pb[0];
            int sb = half * 150;
            for (int s = sb + w; s < sb + 150; s += 8) {
                const float* mrow = g_mem + ((size_t)b * SEQ + s) * D;
                float acc = 0.0f;
                for (int k = lane; k < D; k += 32)
                    acc += s_pw[k] * tanhx(mrow[k] + s_q[k]);
#pragma unroll
                for (int o = 16; o; o >>= 1) acc += __shfl_down_sync(0xffffffffu, acc, o);
                if (lane == 0) g_logits[b * SEQ + s] = acc + pb0;
            }
            __syncthreads();
        } else if (bx < 272) {
            int i = bx - 128, nt = i % 72, kz = i / 72;   // 72 n-tiles x 2 split-K
            pgemm(g_h, nullptr, dWhh, g_part2 + (size_t)(kz * BS) * G,
                  D, D, G, nt * 32, kz * 384, 384, As, Bs);
        }
        grid_barrier();
        // P3: softmax + half-context (128 blocks)
        if (bx < 128) {
            int b = bx >> 1, half = bx & 1;
            float m = -1e30f;
            for (int i = tid; i < SEQ; i += NT) {
                float v = __ldcg(&g_logits[b * SEQ + i]);
                s_w[i] = v;
                m = fmaxf(m, v);
            }
            m = blockReduceMax256(m, red);
            float sum = 0.0f;
            for (int i = tid; i < SEQ; i += NT) {
                float e = __expf(s_w[i] - m);
                s_w[i] = e;
                sum += e;
            }
            sum = blockReduceSum256(sum, red);
            float inv = __fdividef(1.0f, sum);
            float a0 = 0.f, a1 = 0.f, a2 = 0.f;
            int sb = half * 150;
#pragma unroll 2
            for (int s = sb; s < sb + 150; s++) {
                float wv = s_w[s];
                const float* er = g_enc + ((size_t)b * SEQ + s) * D;
                a0 += wv * er[tid];
                a1 += wv * er[tid + 256];
                a2 += wv * er[tid + 512];
            }
            float* cp = &g_ctxp[half][b * D];
            cp[tid]       = a0 * inv;
            cp[tid + 256] = a1 * inv;
            cp[tid + 512] = a2 * inv;
        }
        grid_barrier();
        // P4: gi = ctx @ decWc^T  (A = sum of two ctx halves; 72 n-tiles x 4 split-K)
        {
            int nt = bx % 72, kz = bx / 72;
            pgemm(g_ctxp[0], g_ctxp[1], g_decWc, g_part + (size_t)(kz * BS) * G,
                  D, D, G, nt * 32, kz * 192, 192, As, Bs);
        }
        grid_barrier();
        // P5: gate + prediction (64 blocks)
        if (bx < 64) {
            int b = bx;
            float last = (t == 0) ? 0.0f : __ldcg(&out[b * TSTEPS + t - 1]);
            float psum = 0.0f;
#pragma unroll
            for (int jj = 0; jj < 3; jj++) {
                int j = tid + jj * 256;
                float s0=0.f,s1=0.f,s2=0.f,u0=0.f,u1=0.f,u2=0.f;
#pragma unroll
                for (int z = 0; z < 4; z++) {
                    const float* P = g_part + (size_t)(z * BS + b) * G;
                    s0 += __ldcg(P + j); s1 += __ldcg(P + D + j); s2 += __ldcg(P + 2 * D + j);
                }
#pragma unroll
                for (int z = 0; z < 2; z++) {
                    const float* Q = g_part2 + (size_t)(z * BS + b) * G;
                    u0 += __ldcg(Q + j); u1 += __ldcg(Q + D + j); u2 += __ldcg(Q + 2 * D + j);
                }
                float gir = bih[j]         + last * dWih[(size_t)j * (D + 1)]           + s0;
                float giz = bih[D + j]     + last * dWih[(size_t)(D + j) * (D + 1)]     + s1;
                float gin = bih[2 * D + j] + last * dWih[(size_t)(2 * D + j) * (D + 1)] + s2;
                float r  = sigx(gir + bhh[j] + u0);
                float zt = sigx(giz + bhh[D + j] + u1);
                float n  = tanhx(gin + r * (bhh[2 * D + j] + u2));
                float hp = __ldcg(&g_h[b * D + j]);
                float hn = (1.0f - zt) * n + zt * hp;
                g_h[b * D + j] = hn;
                psum += tW[j] * hn;
            }
            float tot = blockReduceSum256(psum, red);
            if (tid == 0) out[b * TSTEPS + t] = tot + tb[0];
        }
        grid_barrier();
    }
}

// ---------------- launch (5 graph nodes) ----------------
extern "C" void kernel_launch(void* const* d_in, const int* in_sizes, int n_in,
                              void* d_out, int out_size) {
    const float* x        = (const float*)d_in[0];
    const float* enc_Wih  = (const float*)d_in[1];
    const float* enc_Whh  = (const float*)d_in[2];
    const float* enc_bih  = (const float*)d_in[3];
    const float* enc_bhh  = (const float*)d_in[4];
    const float* dec_Wih  = (const float*)d_in[5];
    const float* dec_Whh  = (const float*)d_in[6];
    const float* dec_bih  = (const float*)d_in[7];
    const float* dec_bhh  = (const float*)d_in[8];
    const float* qW       = (const float*)d_in[9];
    const float* qb       = (const float*)d_in[10];
    const float* mW       = (const float*)d_in[11];
    const float* mb       = (const float*)d_in[12];
    const float* pW       = (const float*)d_in[13];
    const float* pb       = (const float*)d_in[14];
    const float* tW       = (const float*)d_in[15];
    const float* tb       = (const float*)d_in[16];
    float* out = (float*)d_out;

    prep_kernel<<<(MTOT * D + 255) / 256, 256>>>(x, dec_Wih);
    sgemm_gi_kernel<<<dim3(G / 64, MTOT / 64), 256>>>(enc_Wih, enc_bih);
    encoder_kernel<<<NB, NT>>>(enc_Whh, enc_bhh);
    sgemm_mem_kernel<<<dim3(D / 64, MTOT / 64), 256>>>(mW, mb);
    decoder_kernel<<<NB, NT>>>(qW, qb, pW, pb, dec_Wih, dec_Whh,
                               dec_bih, dec_bhh, tW, tb, out);
}

// round 6
// speedup vs baseline: 1.4470x; 1.4470x over previous
#include <cuda_runtime.h>
#include <math.h>

#define BS 64
#define SEQ 300
#define D 768
#define G 2304          // 3*D
#define TSTEPS 100
#define MTOT (BS*SEQ)   // 19200
#define NB 288
#define NT 256

// ---------------- device scratch (no allocations allowed) ----------------
__device__ __align__(16) float g_xpe[(size_t)MTOT * D];
__device__ __align__(16) float g_gi [(size_t)MTOT * G];
__device__ __align__(16) float g_enc[(size_t)MTOT * D];
__device__ __align__(16) float g_mem[(size_t)MTOT * D];
__device__ __align__(16) float g_h[BS * D];
__device__ __align__(16) float g_part [4 * BS * G];     // split-K partials (enc gh / dec gi)
__device__ __align__(16) float g_part2[2 * BS * G];     // dec gh partials
__device__ __align__(16) float g_qpart[12 * BS * D];
__device__ __align__(16) float g_logits[BS * SEQ];
__device__ __align__(16) float g_ctxp[2][BS * D];       // ctx halves (softmax-normalized)
__device__ __align__(16) float g_decWc[(size_t)G * D];  // dec_Wih[:,1:] repacked
__device__ unsigned g_bar_count;
__device__ unsigned g_bar_gen;

// ---------------- grid barrier (all blocks co-resident) ----------------
__device__ __forceinline__ void grid_barrier() {
    __syncthreads();
    if (threadIdx.x == 0) {
        __threadfence();
        unsigned gen = *(volatile unsigned*)&g_bar_gen;
        unsigned nb = gridDim.x;
        if (atomicAdd(&g_bar_count, 1u) == nb - 1u) {
            *(volatile unsigned*)&g_bar_count = 0u;
            __threadfence();
            *(volatile unsigned*)&g_bar_gen = gen + 1u;
        } else {
            while (*(volatile unsigned*)&g_bar_gen == gen) { __nanosleep(32); }
        }
    }
    __syncthreads();
}

// ---------------- fast transcendentals (evidence: output insensitive at 1e-7 level) ----
__device__ __forceinline__ float sigx(float x)  { return __fdividef(1.0f, 1.0f + __expf(-x)); }
__device__ __forceinline__ float tanhx(float x) { return 1.0f - __fdividef(2.0f, __expf(2.0f * x) + 1.0f); }

__device__ __forceinline__ float4 ldcg4(const float* p) {
    return __ldcg(reinterpret_cast<const float4*>(p));
}

// ---------------- block reductions (256 threads) ----------------
__device__ __forceinline__ float blockReduceSum256(float v, float* red) {
    __syncthreads();
    int lane = threadIdx.x & 31, w = threadIdx.x >> 5;
#pragma unroll
    for (int o = 16; o; o >>= 1) v += __shfl_down_sync(0xffffffffu, v, o);
    if (lane == 0) red[w] = v;
    __syncthreads();
    if (w == 0) {
        float r = (lane < 8) ? red[lane] : 0.0f;
#pragma unroll
        for (int o = 4; o; o >>= 1) r += __shfl_down_sync(0xffffffffu, r, o);
        if (lane == 0) red[0] = r;
    }
    __syncthreads();
    return red[0];
}

__device__ __forceinline__ float blockReduceMax256(float v, float* red) {
    __syncthreads();
    int lane = threadIdx.x & 31, w = threadIdx.x >> 5;
#pragma unroll
    for (int o = 16; o; o >>= 1) v = fmaxf(v, __shfl_down_sync(0xffffffffu, v, o));
    if (lane == 0) red[w] = v;
    __syncthreads();
    if (w == 0) {
        float r = (lane < 8) ? red[lane] : -1e30f;
#pragma unroll
        for (int o = 4; o; o >>= 1) r = fmaxf(r, __shfl_down_sync(0xffffffffu, r, o));
        if (lane == 0) red[0] = r;
    }
    __syncthreads();
    return red[0];
}

// ---------------- persistent small-M GEMM tile: Cp[64, n0..n0+31] = A[64,kslice] * B^T ----
__device__ void pgemm(const float* __restrict__ A, const float* __restrict__ A2,
                      const float* __restrict__ B, float* __restrict__ Cp,
                      int lda, int ldb, int ldc, int n0, int kbeg, int kc,
                      float (*As)[65], float (*Bs)[36])
{
    const int tid = threadIdx.x;
    const int alr = tid & 63;
    const int alk = (tid >> 6) << 2;
    const int brb = tid & 31;
    const int bkb = ((tid >> 5) & 3) << 2;
    const int tr  = tid >> 3;   // 0..31
    const int tc  = tid & 7;    // 0..7
    float a00=0,a01=0,a02=0,a03=0,a10=0,a11=0,a12=0,a13=0;
    const float* Ap  = A + (size_t)alr * lda + kbeg + alk;
    const float* A2p = A2 ? A2 + (size_t)alr * lda + kbeg + alk : nullptr;
    const float* Bp  = B + (size_t)(n0 + brb) * ldb + kbeg + bkb;

    for (int k0 = 0; k0 < kc; k0 += 16) {
        float4 a4 = ldcg4(Ap + k0);
        if (A2p) { float4 y = ldcg4(A2p + k0); a4.x += y.x; a4.y += y.y; a4.z += y.z; a4.w += y.w; }
        As[alk + 0][alr] = a4.x; As[alk + 1][alr] = a4.y;
        As[alk + 2][alr] = a4.z; As[alk + 3][alr] = a4.w;
        if (tid < 128) {
            float4 b4 = *reinterpret_cast<const float4*>(Bp + k0);
            Bs[bkb + 0][brb] = b4.x; Bs[bkb + 1][brb] = b4.y;
            Bs[bkb + 2][brb] = b4.z; Bs[bkb + 3][brb] = b4.w;
        }
        __syncthreads();
#pragma unroll
        for (int kk = 0; kk < 16; kk++) {
            float r0 = As[kk][2 * tr], r1 = As[kk][2 * tr + 1];
            float4 bv = *reinterpret_cast<const float4*>(&Bs[kk][tc << 2]);
            a00 += r0 * bv.x; a01 += r0 * bv.y; a02 += r0 * bv.z; a03 += r0 * bv.w;
            a10 += r1 * bv.x; a11 += r1 * bv.y; a12 += r1 * bv.z; a13 += r1 * bv.w;
        }
        __syncthreads();
    }
    float4 v0 = make_float4(a00, a01, a02, a03);
    float4 v1 = make_float4(a10, a11, a12, a13);
    *reinterpret_cast<float4*>(&Cp[(size_t)(2 * tr)     * ldc + n0 + (tc << 2)]) = v0;
    *reinterpret_cast<float4*>(&Cp[(size_t)(2 * tr + 1) * ldc + n0 + (tc << 2)]) = v1;
}

// ---------------- prep: PE add + dec_Wih repack + zero h ----------------
__global__ void prep_kernel(const float* __restrict__ x, const float* __restrict__ dWih) {
    size_t idx = (size_t)blockIdx.x * blockDim.x + threadIdx.x;
    if (idx < (size_t)MTOT * D) {
        int k = (int)(idx % D);
        int s = (int)((idx / D) % SEQ);
        const float c = 9.210340371976184f / (float)D;  // ln(10000)/d
        int keven = k & ~1;
        float dv  = expf(-(float)keven * c);
        float arg = (float)s * dv;
        float pe  = (k & 1) ? cosf(arg) : sinf(arg);
        g_xpe[idx] = x[idx] + pe;
    }
    if (idx < (size_t)G * D) {
        int g = (int)(idx / D), k = (int)(idx % D);
        g_decWc[idx] = dWih[(size_t)g * (D + 1) + 1 + k];
    }
    if (idx < BS * D) g_h[idx] = 0.0f;
}

// ---------------- big SGEMM: C[M,N] = A[M,K] * B[N,K]^T + bias[n] ----------------
__device__ __forceinline__ void sgemm_body(const float* __restrict__ A,
                                           const float* __restrict__ B,
                                           const float* __restrict__ bias,
                                           float* __restrict__ C,
                                           int N, int K) {
    __shared__ __align__(16) float As[16][68];
    __shared__ __align__(16) float Bs[16][68];
    const int tid = threadIdx.x;
    const int m0 = blockIdx.y * 64;
    const int n0 = blockIdx.x * 64;
    const int tr = tid >> 4;
    const int tc = tid & 15;
    const int lr = tid >> 2;
    const int lk = (tid & 3) << 2;
    float acc[4][4];
#pragma unroll
    for (int i = 0; i < 4; i++)
#pragma unroll
        for (int j = 0; j < 4; j++) acc[i][j] = 0.0f;

    const float* Arow = A + (size_t)(m0 + lr) * K + lk;
    const float* Brow = B + (size_t)(n0 + lr) * K + lk;

    for (int k0 = 0; k0 < K; k0 += 16) {
        float4 a4 = *(const float4*)(Arow + k0);
        float4 b4 = *(const float4*)(Brow + k0);
        As[lk + 0][lr] = a4.x; As[lk + 1][lr] = a4.y; As[lk + 2][lr] = a4.z; As[lk + 3][lr] = a4.w;
        Bs[lk + 0][lr] = b4.x; Bs[lk + 1][lr] = b4.y; Bs[lk + 2][lr] = b4.z; Bs[lk + 3][lr] = b4.w;
        __syncthreads();
#pragma unroll
        for (int kk = 0; kk < 16; kk++) {
            float4 av = *(const float4*)&As[kk][tr << 2];
            float4 bv = *(const float4*)&Bs[kk][tc << 2];
            float a[4] = {av.x, av.y, av.z, av.w};
            float bb[4] = {bv.x, bv.y, bv.z, bv.w};
#pragma unroll
            for (int i = 0; i < 4; i++)
#pragma unroll
                for (int j = 0; j < 4; j++) acc[i][j] += a[i] * bb[j];
        }
        __syncthreads();
    }
    int n = n0 + (tc << 2);
#pragma unroll
    for (int i = 0; i < 4; i++) {
        float4 v;
        v.x = acc[i][0] + bias[n + 0];
        v.y = acc[i][1] + bias[n + 1];
        v.z = acc[i][2] + bias[n + 2];
        v.w = acc[i][3] + bias[n + 3];
        *(float4*)&C[(size_t)(m0 + (tr << 2) + i) * N + n] = v;
    }
}

__global__ __launch_bounds__(256) void sgemm_gi_kernel(const float* __restrict__ W,
                                                       const float* __restrict__ bias) {
    sgemm_body(g_xpe, W, bias, g_gi, G, D);
}
__global__ __launch_bounds__(256) void sgemm_mem_kernel(const float* __restrict__ W,
                                                        const float* __restrict__ bias) {
    sgemm_body(g_enc, W, bias, g_mem, D, D);
}

// ---------------- persistent encoder: 300 GRU steps ----------------
__global__ __launch_bounds__(NT, 2) void encoder_kernel(const float* __restrict__ Whh,
                                                        const float* __restrict__ bhh)
{
    __shared__ __align__(16) float As[16][65];
    __shared__ __align__(16) float Bs[16][36];
    const int bx = blockIdx.x;
    const int tid = threadIdx.x;
    const int nt = bx % 72, kz = bx / 72;       // 72 n-tiles x 4 split-K
    const int n0 = nt * 32, kbeg = kz * 192;
    float* Cp = g_part + (size_t)(kz * BS) * G;
    const int idx = bx * NT + tid;

    for (int s = 0; s < SEQ; s++) {
        pgemm(g_h, nullptr, Whh, Cp, D, D, G, n0, kbeg, 192, As, Bs);
        grid_barrier();
        if (idx < BS * D) {
            int b = idx / D, j = idx - b * D;
            size_t gib = ((size_t)b * SEQ + s) * G;
            float gr = g_gi[gib + j];
            float gz = g_gi[gib + D + j];
            float gn = g_gi[gib + 2 * D + j];
            float t0 = 0.f, t1 = 0.f, t2 = 0.f;
#pragma unroll
            for (int z = 0; z < 4; z++) {
                const float* P = g_part + (size_t)(z * BS + b) * G;
                t0 += __ldcg(P + j); t1 += __ldcg(P + D + j); t2 += __ldcg(P + 2 * D + j);
            }
            float r  = sigx(gr + bhh[j] + t0);
            float zt = sigx(gz + bhh[D + j] + t1);
            float n  = tanhx(gn + r * (bhh[2 * D + j] + t2));
            float hp = __ldcg(&g_h[idx]);
            float hn = (1.0f - zt) * n + zt * hp;
            g_h[idx] = hn;
            g_enc[((size_t)b * SEQ + s) * D + j] = hn;
        }
        grid_barrier();
    }
}

// ---------------- persistent decoder: 100 steps ----------------
__global__ __launch_bounds__(NT, 2) void decoder_kernel(
    const float* __restrict__ qW,  const float* __restrict__ qb,
    const float* __restrict__ pW,  const float* __restrict__ pb,
    const float* __restrict__ dWih, const float* __restrict__ dWhh,
    const float* __restrict__ bih, const float* __restrict__ bhh,
    const float* __restrict__ tW,  const float* __restrict__ tb,
    float* __restrict__ out)
{
    __shared__ __align__(16) float As[16][65];
    __shared__ __align__(16) float Bs[16][36];
    __shared__ float s_q[D];
    __shared__ float s_pw[D];
    __shared__ float s_w[SEQ];
    __shared__ float red[8];
    const int bx = blockIdx.x, tid = threadIdx.x;

    // CRITICAL FIX: reference decoder starts from h0 = zeros, not the encoder's
    // final hidden state. Zero g_h before the first decoder step.
    {
        const int idx = bx * NT + tid;
        if (idx < BS * D) g_h[idx] = 0.0f;
    }
    grid_barrier();

    for (int t = 0; t < TSTEPS; t++) {
        // P1: qpart = h @ qW^T   (24 n-tiles x 12 split-K)
        {
            int nt = bx % 24, kz = bx / 24;
            pgemm(g_h, nullptr, qW, g_qpart + (size_t)(kz * BS) * D,
                  D, D, D, nt * 32, kz * 64, 64, As, Bs);
        }
        grid_barrier();
        // P2: logits (128 blocks)  ||  gh = h @ dWhh^T (144 blocks)
        if (bx < 128) {
            int b = bx >> 1, half = bx & 1;
            for (int j = tid; j < D; j += NT) {
                float v = qb[j];
#pragma unroll
                for (int z = 0; z < 12; z++) v += __ldcg(&g_qpart[(size_t)(z * BS + b) * D + j]);
                s_q[j]  = v;
                s_pw[j] = pW[j];
            }
            __syncthreads();
            int w = tid >> 5, lane = tid & 31;
            float pb0 = pb[0];
            int sb = half * 150;
            for (int s = sb + w; s < sb + 150; s += 8) {
                const float* mrow = g_mem + ((size_t)b * SEQ + s) * D;
                float acc = 0.0f;
                for (int k = lane; k < D; k += 32)
                    acc += s_pw[k] * tanhx(mrow[k] + s_q[k]);
#pragma unroll
                for (int o = 16; o; o >>= 1) acc += __shfl_down_sync(0xffffffffu, acc, o);
                if (lane == 0) g_logits[b * SEQ + s] = acc + pb0;
            }
            __syncthreads();
        } else if (bx < 272) {
            int i = bx - 128, nt = i % 72, kz = i / 72;   // 72 n-tiles x 2 split-K
            pgemm(g_h, nullptr, dWhh, g_part2 + (size_t)(kz * BS) * G,
                  D, D, G, nt * 32, kz * 384, 384, As, Bs);
        }
        grid_barrier();
        // P3: softmax + half-context (128 blocks)
        if (bx < 128) {
            int b = bx >> 1, half = bx & 1;
            float m = -1e30f;
            for (int i = tid; i < SEQ; i += NT) {
                float v = __ldcg(&g_logits[b * SEQ + i]);
                s_w[i] = v;
                m = fmaxf(m, v);
            }
            m = blockReduceMax256(m, red);
            float sum = 0.0f;
            for (int i = tid; i < SEQ; i += NT) {
                float e = __expf(s_w[i] - m);
                s_w[i] = e;
                sum += e;
            }
            sum = blockReduceSum256(sum, red);
            float inv = __fdividef(1.0f, sum);
            float a0 = 0.f, a1 = 0.f, a2 = 0.f;
            int sb = half * 150;
#pragma unroll 2
            for (int s = sb; s < sb + 150; s++) {
                float wv = s_w[s];
                const float* er = g_enc + ((size_t)b * SEQ + s) * D;
                a0 += wv * er[tid];
                a1 += wv * er[tid + 256];
                a2 += wv * er[tid + 512];
            }
            float* cp = &g_ctxp[half][b * D];
            cp[tid]       = a0 * inv;
            cp[tid + 256] = a1 * inv;
            cp[tid + 512] = a2 * inv;
        }
        grid_barrier();
        // P4: gi = ctx @ decWc^T  (A = sum of two ctx halves; 72 n-tiles x 4 split-K)
        {
            int nt = bx % 72, kz = bx / 72;
            pgemm(g_ctxp[0], g_ctxp[1], g_decWc, g_part + (size_t)(kz * BS) * G,
                  D, D, G, nt * 32, kz * 192, 192, As, Bs);
        }
        grid_barrier();
        // P5: gate + prediction (64 blocks)
        if (bx < 64) {
            int b = bx;
            float last = (t == 0) ? 0.0f : __ldcg(&out[b * TSTEPS + t - 1]);
            float psum = 0.0f;
#pragma unroll
            for (int jj = 0; jj < 3; jj++) {
                int j = tid + jj * 256;
                float s0=0.f,s1=0.f,s2=0.f,u0=0.f,u1=0.f,u2=0.f;
#pragma unroll
                for (int z = 0; z < 4; z++) {
                    const float* P = g_part + (size_t)(z * BS + b) * G;
                    s0 += __ldcg(P + j); s1 += __ldcg(P + D + j); s2 += __ldcg(P + 2 * D + j);
                }
#pragma unroll
                for (int z = 0; z < 2; z++) {
                    const float* Q = g_part2 + (size_t)(z * BS + b) * G;
                    u0 += __ldcg(Q + j); u1 += __ldcg(Q + D + j); u2 += __ldcg(Q + 2 * D + j);
                }
                float gir = bih[j]         + last * dWih[(size_t)j * (D + 1)]           + s0;
                float giz = bih[D + j]     + last * dWih[(size_t)(D + j) * (D + 1)]     + s1;
                float gin = bih[2 * D + j] + last * dWih[(size_t)(2 * D + j) * (D + 1)] + s2;
                float r  = sigx(gir + bhh[j] + u0);
                float zt = sigx(giz + bhh[D + j] + u1);
                float n  = tanhx(gin + r * (bhh[2 * D + j] + u2));
                float hp = __ldcg(&g_h[b * D + j]);
                float hn = (1.0f - zt) * n + zt * hp;
                g_h[b * D + j] = hn;
                psum += tW[j] * hn;
            }
            float tot = blockReduceSum256(psum, red);
            if (tid == 0) out[b * TSTEPS + t] = tot + tb[0];
        }
        grid_barrier();
    }
}

// ---------------- launch (5 graph nodes) ----------------
extern "C" void kernel_launch(void* const* d_in, const int* in_sizes, int n_in,
                              void* d_out, int out_size) {
    const float* x        = (const float*)d_in[0];
    const float* enc_Wih  = (const float*)d_in[1];
    const float* enc_Whh  = (const float*)d_in[2];
    const float* enc_bih  = (const float*)d_in[3];
    const float* enc_bhh  = (const float*)d_in[4];
    const float* dec_Wih  = (const float*)d_in[5];
    const float* dec_Whh  = (const float*)d_in[6];
    const float* dec_bih  = (const float*)d_in[7];
    const float* dec_bhh  = (const float*)d_in[8];
    const float* qW       = (const float*)d_in[9];
    const float* qb       = (const float*)d_in[10];
    const float* mW       = (const float*)d_in[11];
    const float* mb       = (const float*)d_in[12];
    const float* pW       = (const float*)d_in[13];
    const float* pb       = (const float*)d_in[14];
    const float* tW       = (const float*)d_in[15];
    const float* tb       = (const float*)d_in[16];
    float* out = (float*)d_out;

    prep_kernel<<<(MTOT * D + 255) / 256, 256>>>(x, dec_Wih);
    sgemm_gi_kernel<<<dim3(G / 64, MTOT / 64), 256>>>(enc_Wih, enc_bih);
    encoder_kernel<<<NB, NT>>>(enc_Whh, enc_bhh);
    sgemm_mem_kernel<<<dim3(D / 64, MTOT / 64), 256>>>(mW, mb);
    decoder_kernel<<<NB, NT>>>(qW, qb, pW, pb, dec_Wih, dec_Whh,
                               dec_bih, dec_bhh, tW, tb, out);
}

// round 7
// speedup vs baseline: 1.7354x; 1.1993x over previous
#include <cuda_runtime.h>
#include <math.h>

typedef unsigned long long u64;
#define BS 64
#define SEQ 300
#define D 768
#define G 2304
#define TSTEPS 100
#define MTOT (BS*SEQ)
#define NB 144
#define NT 256

__device__ __align__(16) float g_xpe[(size_t)MTOT*D];
__device__ __align__(16) float g_gi [(size_t)MTOT*G];
__device__ __align__(16) float g_enc[(size_t)MTOT*D];
__device__ __align__(16) float g_mem[(size_t)MTOT*D];
__device__ __align__(16) float g_h[BS*D];
__device__ __align__(16) float g_part [16*BS*G];
__device__ __align__(16) float g_part2[12*BS*G];
__device__ __align__(16) float g_qpart[12*BS*D];
__device__ __align__(16) float g_logits[BS*SEQ];
__device__ __align__(16) float g_ctxp[2][BS*D];
__device__ __align__(16) float g_decWc[(size_t)G*D];
__device__ unsigned g_bar_count, g_bar_gen;

__device__ __forceinline__ void grid_barrier() {
    __syncthreads();
    if (threadIdx.x == 0) {
        __threadfence();
        unsigned gen = *(volatile unsigned*)&g_bar_gen;
        if (atomicAdd(&g_bar_count, 1u) == gridDim.x - 1u) {
            *(volatile unsigned*)&g_bar_count = 0u;
            __threadfence();
            *(volatile unsigned*)&g_bar_gen = gen + 1u;
        } else {
            while (*(volatile unsigned*)&g_bar_gen == gen) { }
        }
    }
    __syncthreads();
}

// gates (MUFU ok: only 64x768 per step; validated insensitive)
__device__ __forceinline__ float sigx(float x)  { return __fdividef(1.0f, 1.0f + __expf(-x)); }
__device__ __forceinline__ float tanhx(float x) { return 1.0f - __fdividef(2.0f, __expf(2.0f*x) + 1.0f); }

// FMA-pipe-only tanh (Eigen/XLA rational; reciprocal via bit-trick + 3 Newton)
__device__ __forceinline__ float rcp_fma(float d) {
    float r = __uint_as_float(0x7EF477D5u - __float_as_uint(d));
    r = r * fmaf(-d, r, 2.0f);
    r = r * fmaf(-d, r, 2.0f);
    r = r * fmaf(-d, r, 2.0f);
    return r;
}
__device__ __forceinline__ float tanh_fma(float x) {
    x = fminf(fmaxf(x, -7.90531110763549805f), 7.90531110763549805f);
    float x2 = x * x;
    float p = fmaf(x2, -2.76076847742355e-16f, 2.00018790482477e-13f);
    p = fmaf(x2, p, -8.60467152213735e-11f);
    p = fmaf(x2, p,  5.12229709037114e-08f);
    p = fmaf(x2, p,  1.48572235717979e-05f);
    p = fmaf(x2, p,  6.37261928875436e-04f);
    p = fmaf(x2, p,  4.89352455891786e-03f);
    float q = fmaf(x2, 1.19825839466702e-06f, 1.18534705686654e-04f);
    q = fmaf(x2, q, 2.26843463243900e-03f);
    q = fmaf(x2, q, 4.89352518554385e-03f);
    return (x * p) * rcp_fma(q);
}

__device__ __forceinline__ float4 ldcg4(const float* p) {
    return __ldcg(reinterpret_cast<const float4*>(p));
}
__device__ __forceinline__ u64 dup2(float a) {
    u64 r; asm("mov.b64 %0, {%1, %1};" : "=l"(r) : "f"(a)); return r;
}
__device__ __forceinline__ u64 ffma2(u64 a, u64 b, u64 c) {
    u64 d; asm("fma.rn.f32x2 %0, %1, %2, %3;" : "=l"(d) : "l"(a), "l"(b), "l"(c)); return d;
}
__device__ __forceinline__ float4 f4of(u64 a, u64 b) {
    float4 v;
    asm("mov.b64 {%0, %1}, %2;" : "=f"(v.x), "=f"(v.y) : "l"(a));
    asm("mov.b64 {%0, %1}, %2;" : "=f"(v.z), "=f"(v.w) : "l"(b));
    return v;
}
#define FF8(i, aval) do { u64 ad_ = dup2(aval); \
    acc[i][0] = ffma2(ad_, b01.x, acc[i][0]); \
    acc[i][1] = ffma2(ad_, b01.y, acc[i][1]); \
    acc[i][2] = ffma2(ad_, b23.x, acc[i][2]); \
    acc[i][3] = ffma2(ad_, b23.y, acc[i][3]); } while (0)

__device__ __forceinline__ float redSum(float v, float* red) {
    __syncthreads();
    int lane = threadIdx.x & 31, w = threadIdx.x >> 5;
#pragma unroll
    for (int o = 16; o; o >>= 1) v += __shfl_down_sync(0xffffffffu, v, o);
    if (lane == 0) red[w] = v;
    __syncthreads();
    if (w == 0) {
        float r = (lane < 8) ? red[lane] : 0.0f;
#pragma unroll
        for (int o = 4; o; o >>= 1) r += __shfl_down_sync(0xffffffffu, r, o);
        if (lane == 0) red[0] = r;
    }
    __syncthreads();
    return red[0];
}
__device__ __forceinline__ float redMax(float v, float* red) {
    __syncthreads();
    int lane = threadIdx.x & 31, w = threadIdx.x >> 5;
#pragma unroll
    for (int o = 16; o; o >>= 1) v = fmaxf(v, __shfl_down_sync(0xffffffffu, v, o));
    if (lane == 0) red[w] = v;
    __syncthreads();
    if (w == 0) {
        float r = (lane < 8) ? red[lane] : -1e30f;
#pragma unroll
        for (int o = 4; o; o >>= 1) r = fmaxf(r, __shfl_down_sync(0xffffffffu, r, o));
        if (lane == 0) red[0] = r;
    }
    __syncthreads();
    return red[0];
}

// ---- small-M GEMM (f32x2): Cp[64, n0..n0+255] = (A[+A2])[64,kslice] @ B^T, 256 thr ----
__device__ void gemm64_f2(const float* __restrict__ A, const float* __restrict__ A2,
                          const float* __restrict__ B, float* __restrict__ Cp,
                          int lda, int ldb, int ldc, int n0, int kbeg, int kc,
                          float* As, float* Bs)
{
    const int tid = threadIdx.x, ty = tid >> 5, tx = tid & 31;
    const int am = tid & 63, akq = (tid >> 6) & 1;
    const bool ald = tid < 128;
    u64 acc[8][4];
#pragma unroll
    for (int i = 0; i < 8; i++)
#pragma unroll
        for (int j = 0; j < 4; j++) acc[i][j] = 0ull;
    const float* Ap  = A + (size_t)am * lda + kbeg + akq * 4;
    const float* A2p = A2 ? A2 + (size_t)am * lda + kbeg + akq * 4 : (const float*)0;
    const float* Bp  = B + (size_t)(n0 + tid) * ldb + kbeg;
    const int nst = kc >> 3;
    float4 va, vb0, vb1;
    if (ald) { va = ldcg4(Ap);
        if (A2p) { float4 y = ldcg4(A2p); va.x += y.x; va.y += y.y; va.z += y.z; va.w += y.w; } }
    vb0 = *(const float4*)Bp; vb1 = *(const float4*)(Bp + 4);
    if (ald) { As[(akq*4+0)*68+am]=va.x; As[(akq*4+1)*68+am]=va.y;
               As[(akq*4+2)*68+am]=va.z; As[(akq*4+3)*68+am]=va.w; }
    Bs[0*260+tid]=vb0.x; Bs[1*260+tid]=vb0.y; Bs[2*260+tid]=vb0.z; Bs[3*260+tid]=vb0.w;
    Bs[4*260+tid]=vb1.x; Bs[5*260+tid]=vb1.y; Bs[6*260+tid]=vb1.z; Bs[7*260+tid]=vb1.w;
    __syncthreads();
    for (int st = 0; st < nst; st++) {
        if (st + 1 < nst) {
            if (ald) { va = ldcg4(Ap + (st+1)*8);
                if (A2p) { float4 y = ldcg4(A2p + (st+1)*8); va.x+=y.x; va.y+=y.y; va.z+=y.z; va.w+=y.w; } }
            vb0 = *(const float4*)(Bp + (st+1)*8); vb1 = *(const float4*)(Bp + (st+1)*8 + 4);
        }
        const float* Asl = As + (st & 1) * 544;
        const float* Bsl = Bs + (st & 1) * 2080;
#pragma unroll
        for (int kk = 0; kk < 8; kk++) {
            float4 a0 = *(const float4*)(Asl + kk*68 + ty*4);
            float4 a1 = *(const float4*)(Asl + kk*68 + 32 + ty*4);
            ulonglong2 b01 = *(const ulonglong2*)(Bsl + kk*260 + tx*4);
            ulonglong2 b23 = *(const ulonglong2*)(Bsl + kk*260 + 128 + tx*4);
            FF8(0, a0.x); FF8(1, a0.y); FF8(2, a0.z); FF8(3, a0.w);
            FF8(4, a1.x); FF8(5, a1.y); FF8(6, a1.z); FF8(7, a1.w);
        }
        if (st + 1 < nst) {
            float* An = As + ((st+1) & 1) * 544;
            float* Bn = Bs + ((st+1) & 1) * 2080;
            if (ald) { An[(akq*4+0)*68+am]=va.x; An[(akq*4+1)*68+am]=va.y;
                       An[(akq*4+2)*68+am]=va.z; An[(akq*4+3)*68+am]=va.w; }
            Bn[0*260+tid]=vb0.x; Bn[1*260+tid]=vb0.y; Bn[2*260+tid]=vb0.z; Bn[3*260+tid]=vb0.w;
            Bn[4*260+tid]=vb1.x; Bn[5*260+tid]=vb1.y; Bn[6*260+tid]=vb1.z; Bn[7*260+tid]=vb1.w;
            __syncthreads();
        }
    }
#pragma unroll
    for (int i = 0; i < 8; i++) {
        int r = (i < 4) ? (ty*4 + i) : (32 + ty*4 + i - 4);
        float* cr = Cp + (size_t)r * ldc + n0;
        *(float4*)(cr + tx*4)       = f4of(acc[i][0], acc[i][1]);
        *(float4*)(cr + 128 + tx*4) = f4of(acc[i][2], acc[i][3]);
    }
}

// ---- big GEMM (f32x2, 128x128 tile): C = A @ B^T + bias ----
__device__ __forceinline__ void sgemm_f2_body(const float* __restrict__ A,
                                              const float* __restrict__ B,
                                              const float* __restrict__ bias,
                                              float* __restrict__ C, int N, int K)
{
    __shared__ __align__(16) float As[2112];
    __shared__ __align__(16) float Bs[2112];
    const int tid = threadIdx.x, ty = tid >> 4, tx = tid & 15;
    const int m0 = blockIdx.y << 7, n0 = blockIdx.x << 7;
    const int lm = tid & 127, lkq = tid >> 7;
    u64 acc[8][4];
#pragma unroll
    for (int i = 0; i < 8; i++)
#pragma unroll
        for (int j = 0; j < 4; j++) acc[i][j] = 0ull;
    const float* Ap = A + (size_t)(m0 + lm) * K + lkq * 4;
    const float* Bp = B + (size_t)(n0 + lm) * K + lkq * 4;
    const int nst = K >> 3;
    float4 va = *(const float4*)Ap, vb = *(const float4*)Bp;
    As[(lkq*4+0)*132+lm]=va.x; As[(lkq*4+1)*132+lm]=va.y;
    As[(lkq*4+2)*132+lm]=va.z; As[(lkq*4+3)*132+lm]=va.w;
    Bs[(lkq*4+0)*132+lm]=vb.x; Bs[(lkq*4+1)*132+lm]=vb.y;
    Bs[(lkq*4+2)*132+lm]=vb.z; Bs[(lkq*4+3)*132+lm]=vb.w;
    __syncthreads();
    for (int st = 0; st < nst; st++) {
        if (st + 1 < nst) {
            va = *(const float4*)(Ap + (st+1)*8);
            vb = *(const float4*)(Bp + (st+1)*8);
        }
        const float* Asl = As + (st & 1) * 1056;
        const float* Bsl = Bs + (st & 1) * 1056;
#pragma unroll
        for (int kk = 0; kk < 8; kk++) {
            float4 a0 = *(const float4*)(Asl + kk*132 + ty*4);
            float4 a1 = *(const float4*)(Asl + kk*132 + 64 + ty*4);
            ulonglong2 b01 = *(const ulonglong2*)(Bsl + kk*132 + tx*4);
            ulonglong2 b23 = *(const ulonglong2*)(Bsl + kk*132 + 64 + tx*4);
            FF8(0, a0.x); FF8(1, a0.y); FF8(2, a0.z); FF8(3, a0.w);
            FF8(4, a1.x); FF8(5, a1.y); FF8(6, a1.z); FF8(7, a1.w);
        }
        if (st + 1 < nst) {
            float* An = As + ((st+1) & 1) * 1056;
            float* Bn = Bs + ((st+1) & 1) * 1056;
            An[(lkq*4+0)*132+lm]=va.x; An[(lkq*4+1)*132+lm]=va.y;
            An[(lkq*4+2)*132+lm]=va.z; An[(lkq*4+3)*132+lm]=va.w;
            Bn[(lkq*4+0)*132+lm]=vb.x; Bn[(lkq*4+1)*132+lm]=vb.y;
            Bn[(lkq*4+2)*132+lm]=vb.z; Bn[(lkq*4+3)*132+lm]=vb.w;
            __syncthreads();
        }
    }
    const int c0 = n0 + tx*4, c1 = n0 + 64 + tx*4;
    float4 bi0 = *(const float4*)(bias + c0);
    float4 bi1 = *(const float4*)(bias + c1);
#pragma unroll
    for (int i = 0; i < 8; i++) {
        int r = m0 + ((i < 4) ? (ty*4 + i) : (64 + ty*4 + i - 4));
        float4 v0 = f4of(acc[i][0], acc[i][1]);
        float4 v1 = f4of(acc[i][2], acc[i][3]);
        v0.x += bi0.x; v0.y += bi0.y; v0.z += bi0.z; v0.w += bi0.w;
        v1.x += bi1.x; v1.y += bi1.y; v1.z += bi1.z; v1.w += bi1.w;
        *(float4*)(C + (size_t)r * N + c0) = v0;
        *(float4*)(C + (size_t)r * N + c1) = v1;
    }
}

__global__ __launch_bounds__(256, 2) void sgemm_gi_kernel(const float* __restrict__ W,
                                                          const float* __restrict__ bias) {
    sgemm_f2_body(g_xpe, W, bias, g_gi, G, D);
}
__global__ __launch_bounds__(256, 2) void sgemm_mem_kernel(const float* __restrict__ W,
                                                           const float* __restrict__ bias) {
    sgemm_f2_body(g_enc, W, bias, g_mem, D, D);
}

__global__ void prep_kernel(const float* __restrict__ x, const float* __restrict__ dWih) {
    size_t idx = (size_t)blockIdx.x * blockDim.x + threadIdx.x;
    if (idx < (size_t)MTOT * D) {
        int k = (int)(idx % D);
        int s = (int)((idx / D) % SEQ);
        const float c = 9.210340371976184f / (float)D;
        float dv  = expf(-(float)(k & ~1) * c);
        float arg = (float)s * dv;
        g_xpe[idx] = x[idx] + ((k & 1) ? cosf(arg) : sinf(arg));
    }
    if (idx < (size_t)G * D) {
        int g = (int)(idx / D), k = (int)(idx % D);
        g_decWc[idx] = dWih[(size_t)g * (D + 1) + 1 + k];
    }
    if (idx < BS * D) g_h[idx] = 0.0f;
}

// ---- persistent encoder ----
__global__ __launch_bounds__(NT) void encoder_kernel(const float* __restrict__ Whh,
                                                     const float* __restrict__ bhh)
{
    __shared__ __align__(16) float As[1088];
    __shared__ __align__(16) float Bs[4160];
    const int bx = blockIdx.x, tid = threadIdx.x;
    const int nt = bx >> 4, kz = bx & 15;    // 9 n-tiles(256) x 16 split-K(48)
    float* Cp = g_part + (size_t)kz * BS * G;
    for (int s = 0; s < SEQ; s++) {
        gemm64_f2(g_h, 0, Whh, Cp, D, D, G, nt << 8, kz * 48, 48, As, Bs);
        grid_barrier();
#pragma unroll
        for (int e = 0; e < 2; e++) {
            int idx = bx * NT + tid + e * (NB * NT);
            if (idx < BS * D) {
                int b = idx / D, j = idx - b * D;
                size_t gib = ((size_t)b * SEQ + s) * G;
                float t0 = 0.f, t1 = 0.f, t2 = 0.f;
#pragma unroll
                for (int z = 0; z < 16; z++) {
                    const float* P = g_part + (size_t)(z * BS + b) * G;
                    t0 += __ldcg(P + j); t1 += __ldcg(P + D + j); t2 += __ldcg(P + 2*D + j);
                }
                float r  = sigx(g_gi[gib + j] + bhh[j] + t0);
                float zt = sigx(g_gi[gib + D + j] + bhh[D + j] + t1);
                float n  = tanhx(g_gi[gib + 2*D + j] + r * (bhh[2*D + j] + t2));
                float hp = __ldcg(&g_h[idx]);
                float hn = (1.0f - zt) * n + zt * hp;
                g_h[idx] = hn;
                g_enc[((size_t)b * SEQ + s) * D + j] = hn;
            }
        }
        grid_barrier();
    }
}

// ---- persistent decoder ----
__global__ __launch_bounds__(NT) void decoder_kernel(
    const float* __restrict__ qW,  const float* __restrict__ qb,
    const float* __restrict__ pW,  const float* __restrict__ pb,
    const float* __restrict__ dWih, const float* __restrict__ dWhh,
    const float* __restrict__ bih, const float* __restrict__ bhh,
    const float* __restrict__ tW,  const float* __restrict__ tb,
    float* __restrict__ out)
{
    __shared__ __align__(16) float As[1088];
    __shared__ __align__(16) float Bs[4160];
    __shared__ __align__(16) float s_q[D];
    __shared__ __align__(16) float s_pw[D];
    __shared__ float s_w[SEQ];
    __shared__ float red[8];
    const int bx = blockIdx.x, tid = threadIdx.x;

    // decoder h0 = zeros
#pragma unroll
    for (int e = 0; e < 2; e++) {
        int idx = bx * NT + tid + e * (NB * NT);
        if (idx < BS * D) g_h[idx] = 0.0f;
    }
    grid_barrier();

    for (int t = 0; t < TSTEPS; t++) {
        // P1: fused q + gh GEMMs (12 n-tiles x 12 split-K over stacked [qW; dWhh])
        {
            int nt = bx / 12, kz = bx % 12;
            const float* Bsel; float* Cp; int n0s, ldcs;
            if (nt < 3) { Bsel = qW;   n0s = nt * 256;       Cp = g_qpart + (size_t)kz * BS * D; ldcs = D; }
            else        { Bsel = dWhh; n0s = (nt - 3) * 256; Cp = g_part2 + (size_t)kz * BS * G; ldcs = G; }
            gemm64_f2(g_h, 0, Bsel, Cp, D, D, ldcs, n0s, kz * 64, 64, As, Bs);
        }
        grid_barrier();
        // P2: attention logits (128 blocks), tanh on FMA pipe
        if (bx < 128) {
            int b = bx >> 1, half = bx & 1;
            for (int j = tid; j < D; j += NT) {
                float v = qb[j];
#pragma unroll
                for (int z = 0; z < 12; z++) v += __ldcg(&g_qpart[(size_t)(z * BS + b) * D + j]);
                s_q[j]  = v;
                s_pw[j] = pW[j];
            }
            __syncthreads();
            int w = tid >> 5, lane = tid & 31;
            float pb0 = pb[0];
            int sb = half * 150;
            for (int s = sb + w; s < sb + 150; s += 8) {
                const float* mrow = g_mem + ((size_t)b * SEQ + s) * D;
                float acc = 0.0f;
#pragma unroll 2
                for (int k = lane * 4; k < D; k += 128) {
                    float4 m4 = ldcg4(mrow + k);
                    float4 q4 = *(const float4*)&s_q[k];
                    float4 w4 = *(const float4*)&s_pw[k];
                    acc += w4.x * tanh_fma(m4.x + q4.x);
                    acc += w4.y * tanh_fma(m4.y + q4.y);
                    acc += w4.z * tanh_fma(m4.z + q4.z);
                    acc += w4.w * tanh_fma(m4.w + q4.w);
                }
#pragma unroll
                for (int o = 16; o; o >>= 1) acc += __shfl_down_sync(0xffffffffu, acc, o);
                if (lane == 0) g_logits[b * SEQ + s] = acc + pb0;
            }
        }
        grid_barrier();
        // P3: softmax + half-context (128 blocks)
        if (bx < 128) {
            int b = bx >> 1, half = bx & 1;
            float m = -1e30f;
            for (int i = tid; i < SEQ; i += NT) {
                float v = __ldcg(&g_logits[b * SEQ + i]);
                s_w[i] = v;
                m = fmaxf(m, v);
            }
            m = redMax(m, red);
            float sum = 0.0f;
            for (int i = tid; i < SEQ; i += NT) {
                float e = __expf(s_w[i] - m);
                s_w[i] = e;
                sum += e;
            }
            sum = redSum(sum, red);
            float inv = __fdividef(1.0f, sum);
            if (tid < 192) {
                float4 c4 = make_float4(0.f, 0.f, 0.f, 0.f);
                int sb = half * 150;
                const float* ep = g_enc + ((size_t)b * SEQ + sb) * D + tid * 4;
#pragma unroll 2
                for (int s = 0; s < 150; s++) {
                    float wv = s_w[sb + s];
                    float4 e4 = ldcg4(ep + (size_t)s * D);
                    c4.x += wv * e4.x; c4.y += wv * e4.y;
                    c4.z += wv * e4.z; c4.w += wv * e4.w;
                }
                c4.x *= inv; c4.y *= inv; c4.z *= inv; c4.w *= inv;
                *(float4*)&g_ctxp[half][b * D + tid * 4] = c4;
            }
        }
        grid_barrier();
        // P4: gi = (ctx0+ctx1) @ decWc^T  (9 n-tiles x 16 split-K)
        {
            int nt = bx >> 4, kz = bx & 15;
            gemm64_f2(g_ctxp[0], g_ctxp[1], g_decWc, g_part + (size_t)kz * BS * G,
                      D, D, G, nt << 8, kz * 48, 48, As, Bs);
        }
        grid_barrier();
        // P5: gate + prediction (64 blocks)
        if (bx < 64) {
            int b = bx;
            float last = (t == 0) ? 0.0f : __ldcg(&out[b * TSTEPS + t - 1]);
            float psum = 0.0f;
#pragma unroll
            for (int jj = 0; jj < 3; jj++) {
                int j = tid + jj * NT;
                float s0 = 0.f, s1 = 0.f, s2 = 0.f, u0 = 0.f, u1 = 0.f, u2 = 0.f;
#pragma unroll
                for (int z = 0; z < 16; z++) {
                    const float* P = g_part + (size_t)(z * BS + b) * G;
                    s0 += __ldcg(P + j); s1 += __ldcg(P + D + j); s2 += __ldcg(P + 2*D + j);
                }
#pragma unroll
                for (int z = 0; z < 12; z++) {
                    const float* Q = g_part2 + (size_t)(z * BS + b) * G;
                    u0 += __ldcg(Q + j); u1 += __ldcg(Q + D + j); u2 += __ldcg(Q + 2*D + j);
                }
                float gir = bih[j]       + last * dWih[(size_t)j * (D+1)]         + s0;
                float giz = bih[D + j]   + last * dWih[(size_t)(D + j) * (D+1)]   + s1;
                float gin = bih[2*D + j] + last * dWih[(size_t)(2*D + j) * (D+1)] + s2;
                float r  = sigx(gir + bhh[j] + u0);
                float zt = sigx(giz + bhh[D + j] + u1);
                float n  = tanhx(gin + r * (bhh[2*D + j] + u2));
                float hp = __ldcg(&g_h[b * D + j]);
                float hn = (1.0f - zt) * n + zt * hp;
                g_h[b * D + j] = hn;
                psum += tW[j] * hn;
            }
            float tot = redSum(psum, red);
            if (tid == 0) out[b * TSTEPS + t] = tot + tb[0];
        }
        grid_barrier();
    }
}

extern "C" void kernel_launch(void* const* d_in, const int* in_sizes, int n_in,
                              void* d_out, int out_size) {
    const float* x       = (const float*)d_in[0];
    const float* enc_Wih = (const float*)d_in[1];
    const float* enc_Whh = (const float*)d_in[2];
    const float* enc_bih = (const float*)d_in[3];
    const float* enc_bhh = (const float*)d_in[4];
    const float* dec_Wih = (const float*)d_in[5];
    const float* dec_Whh = (const float*)d_in[6];
    const float* dec_bih = (const float*)d_in[7];
    const float* dec_bhh = (const float*)d_in[8];
    const float* qW      = (const float*)d_in[9];
    const float* qb      = (const float*)d_in[10];
    const float* mW      = (const float*)d_in[11];
    const float* mb      = (const float*)d_in[12];
    const float* pW      = (const float*)d_in[13];
    const float* pb      = (const float*)d_in[14];
    const float* tW      = (const float*)d_in[15];
    const float* tb      = (const float*)d_in[16];
    float* out = (float*)d_out;

    prep_kernel<<<(MTOT * D + 255) / 256, 256>>>(x, dec_Wih);
    sgemm_gi_kernel<<<dim3(G / 128, MTOT / 128), 256>>>(enc_Wih, enc_bih);
    encoder_kernel<<<NB, NT>>>(enc_Whh, enc_bhh);
    sgemm_mem_kernel<<<dim3(D / 128, MTOT / 128), 256>>>(mW, mb);
    decoder_kernel<<<NB, NT>>>(qW, qb, pW, pb, dec_Wih, dec_Whh,
                               dec_bih, dec_bhh, tW, tb, out);
}